// round 15
// baseline (speedup 1.0000x reference)
#include <cuda_runtime.h>
#include <cuda_fp16.h>
#include <cstdint>

// Problem constants
#define N_NODES 50000
#define D_FEAT  128
#define K_TOT   256
#define MT      128
#define NCTA    ((N_NODES + MT - 1) / MT)   // 391
#define TILE_B  16384                        // one [128 x 64] fp16 tile image

// X tile images (fp16): per gemm-CTA b, kt0/1 = feat, kt2/3 = agg.
__device__ __align__(16) uint8_t g_xh_img[(size_t)NCTA * 4 * TILE_B];
__device__ __align__(16) uint8_t g_Wh_img[4 * TILE_B];
__device__ __align__(16) uint8_t g_Wl_img[4 * TILE_B];
__device__ int g_row_ptr[N_NODES + 1];

// ===========================================================================
// Helpers
// ===========================================================================
__device__ __forceinline__ uint32_t smem_u32(const void* p) {
    uint32_t a;
    asm("{ .reg .u64 t; cvta.to.shared.u64 t, %1; cvt.u32.u64 %0, t; }"
        : "=r"(a) : "l"(p));
    return a;
}
#define SWZ128(off) ((off) ^ (((off) >> 3) & 0x70))

__device__ __forceinline__ uint32_t pack_h2(float a, float b) {
    __half2 h = __floats2half2_rn(a, b);
    return *reinterpret_cast<uint32_t*>(&h);
}
__device__ __forceinline__ void ldsm_x4(uint32_t r[4], uint32_t addr) {
    asm volatile("ldmatrix.sync.aligned.m8n8.x4.shared.b16 {%0,%1,%2,%3}, [%4];"
                 : "=r"(r[0]), "=r"(r[1]), "=r"(r[2]), "=r"(r[3]) : "r"(addr));
}
__device__ __forceinline__ void mma_f16(float c[4], const uint32_t a[4],
                                        uint32_t b0, uint32_t b1) {
    asm volatile(
        "mma.sync.aligned.m16n8k16.row.col.f32.f16.f16.f32 "
        "{%0,%1,%2,%3}, {%4,%5,%6,%7}, {%8,%9}, {%0,%1,%2,%3};"
        : "+f"(c[0]), "+f"(c[1]), "+f"(c[2]), "+f"(c[3])
        : "r"(a[0]), "r"(a[1]), "r"(a[2]), "r"(a[3]), "r"(b0), "r"(b1));
}
__device__ __forceinline__ void cp_async16(uint32_t smem, const void* gmem) {
    asm volatile("cp.async.cg.shared.global [%0], [%1], 16;\n"
                 :: "r"(smem), "l"(gmem));
}
__device__ __forceinline__ void cp_commit() {
    asm volatile("cp.async.commit_group;\n" ::);
}
template <int N>
__device__ __forceinline__ void cp_wait() {
    asm volatile("cp.async.wait_group %0;\n" :: "n"(N));
}
__device__ __forceinline__ uint2 hi4(float4 v) {
    return make_uint2(pack_h2(v.x, v.y), pack_h2(v.z, v.w));
}

// ===========================================================================
// Kernel 1 (fused, independent parts): rowptr | featprep | wprep
// ===========================================================================
__global__ __launch_bounds__(256) void prep1_kernel(
    const float4* __restrict__ feat4,
    const int*    __restrict__ dst,
    const float*  __restrict__ W,
    int n_nodes, int n_edges, int rpb, int fpb)
{
    const int bid = blockIdx.x;
    const int tid = threadIdx.x;

    if (bid < rpb) {
        // ---- rowptr: 4 edges per thread ----
        int e4 = bid * 256 + tid;
        int e0 = e4 * 4;
        if (e0 >= n_edges) return;
        int v0, v1, v2, v3;
        if (e0 + 3 < n_edges) {
            int4 d = __ldg(reinterpret_cast<const int4*>(dst) + e4);
            v0 = d.x; v1 = d.y; v2 = d.z; v3 = d.w;
        } else {
            v0 = __ldg(dst + e0);
            v1 = (e0 + 1 < n_edges) ? __ldg(dst + e0 + 1) : v0;
            v2 = (e0 + 2 < n_edges) ? __ldg(dst + e0 + 2) : v1;
            v3 = (e0 + 3 < n_edges) ? __ldg(dst + e0 + 3) : v2;
        }
        int dp = (e0 == 0) ? -1 : __ldg(dst + e0 - 1);
        int vals[5] = {dp, v0, v1, v2, v3};
#pragma unroll
        for (int j = 0; j < 4; ++j)
            if (e0 + j < n_edges)
                for (int v = vals[j] + 1; v <= vals[j + 1]; ++v)
                    g_row_ptr[v] = e0 + j;
        if (e0 + 4 >= n_edges) {
            int last = vals[4 - (e0 + 4 - n_edges)];
            for (int v = last + 1; v <= n_nodes; ++v) g_row_ptr[v] = n_edges;
        }
    } else if (bid < rpb + fpb) {
        // ---- featprep: thread owns (node v, 8 k's) -> one 16B store ----
        int base  = (bid - rpb) * 1024 + tid;
        int total = n_nodes * 16;
#pragma unroll
        for (int i = 0; i < 4; ++i) {
            int idx = base + i * 256;
            if (idx < total) {
                int v  = idx >> 4;
                int c8 = idx & 15;          // 8-k group
                float4 f0 = __ldg(feat4 + (size_t)v * 32 + c8 * 2);
                float4 f1 = __ldg(feat4 + (size_t)v * 32 + c8 * 2 + 1);
                uint2 h0 = hi4(f0), h1 = hi4(f1);
                int b   = v >> 7;
                int row = v & 127;
                int t   = c8 >> 3;          // tile kt0/1
                uint32_t off = SWZ128((uint32_t)(row * 128 + (c8 & 7) * 16));
                uint4 val = make_uint4(h0.x, h0.y, h1.x, h1.y);
                *reinterpret_cast<uint4*>(
                    g_xh_img + ((size_t)b * 4 + t) * TILE_B + off) = val;
            }
        }
    } else {
        // ---- wprep: fp16 hi/lo ----
        for (int idx = (bid - rpb - fpb) * 256 + tid; idx < K_TOT * D_FEAT;
             idx += 16 * 256) {
            int n = idx & 127;
            int k = idx >> 7;
            float w = __ldg(W + (size_t)k * D_FEAT + n);
            __half h = __float2half(w);
            __half l = __float2half(w - __half2float(h));
            int kt = k >> 6;
            int kc = k & 63;
            uint32_t off = SWZ128((uint32_t)(n * 128 + kc * 2));
            *reinterpret_cast<__half*>(g_Wh_img + kt * TILE_B + off) = h;
            *reinterpret_cast<__half*>(g_Wl_img + kt * TILE_B + off) = l;
        }
    }
}

// ===========================================================================
// Kernel 2: warp-per-node segmented reduction with cp.async-staged gathers.
// Each cp.async instruction stages 2 edges (32 lanes x 16B = 2 x 256B rows)
// into a per-warp 2-slot smem ring; consume via LDS + FMA. Outstanding
// copies cost no registers -> gather becomes L2-throughput bound.
// ===========================================================================
struct Pend { int s0, s1; float a0, a1; };

__device__ __forceinline__ Pend stage_pair(
    const int* __restrict__ src, const float* __restrict__ affine,
    int ep, uint32_t slot, int lane)
{
    Pend p;
    p.s0 = __ldg(src + ep);     p.s1 = __ldg(src + ep + 1);
    p.a0 = __ldg(affine + ep);  p.a1 = __ldg(affine + ep + 1);
    int s = (lane < 16) ? p.s0 : p.s1;
    uint32_t tile = ((uint32_t)lane >> 3) & 1;
    const uint8_t* g = g_xh_img + ((size_t)(s >> 7) * 4 + tile) * TILE_B
                     + (uint32_t)(s & 127) * 128 + ((uint32_t)lane & 7) * 16;
    uint32_t d = slot + (((uint32_t)lane >> 4) << 8) + (tile << 7)
               + (((uint32_t)lane & 7) << 4);
    cp_async16(d, g);
    return p;
}

// lane's within-slot offset for an edge with source node s
__device__ __forceinline__ uint32_t off_in_slot(int s, int lane) {
    return (((uint32_t)lane >> 4) << 7)
         + ((((uint32_t)lane & 15) * 8u) ^ (((uint32_t)s & 7) << 4));
}

__device__ __forceinline__ void acc_lds(float4& acc, uint32_t saddr, float a) {
    uint32_t d0, d1;
    asm volatile("ld.shared.v2.u32 {%0,%1}, [%2];"
                 : "=r"(d0), "=r"(d1) : "r"(saddr));
    float2 f01 = __half22float2(*reinterpret_cast<const __half2*>(&d0));
    float2 f23 = __half22float2(*reinterpret_cast<const __half2*>(&d1));
    acc.x = fmaf(f01.x, a, acc.x);
    acc.y = fmaf(f01.y, a, acc.y);
    acc.z = fmaf(f23.x, a, acc.z);
    acc.w = fmaf(f23.y, a, acc.w);
}

// scalar-LDG fallback for remainder edges
__device__ __forceinline__ void acc_gmem(float4& acc, int s, float a, int lane) {
    const uint32_t tq = ((uint32_t)lane >> 4) * TILE_B
                      + ((uint32_t)lane & 15) * 8;
    const uint8_t* p = g_xh_img + ((size_t)(s >> 7) * 4) * TILE_B
        + (uint32_t)(s & 127) * 128 + (tq ^ (((uint32_t)s & 7) << 4));
    uint2 d = *reinterpret_cast<const uint2*>(p);
    float2 f01 = __half22float2(*reinterpret_cast<const __half2*>(&d.x));
    float2 f23 = __half22float2(*reinterpret_cast<const __half2*>(&d.y));
    acc.x = fmaf(f01.x, a, acc.x);
    acc.y = fmaf(f01.y, a, acc.y);
    acc.z = fmaf(f23.x, a, acc.z);
    acc.w = fmaf(f23.y, a, acc.w);
}

__global__ __launch_bounds__(256) void agg_kernel(
    const float* __restrict__ affine,
    const int*   __restrict__ src,
    int n_nodes)
{
    __shared__ __align__(16) uint8_t sbuf[8 * 1024];   // 8 warps x 2 slots x 512B

    int warp = (blockIdx.x * blockDim.x + threadIdx.x) >> 5;
    int lane = threadIdx.x & 31;
    if (warp >= n_nodes) return;

    const int wloc = (threadIdx.x >> 5);
    const uint32_t slotA = smem_u32(sbuf) + (uint32_t)wloc * 1024u;
    const uint32_t slotB = slotA + 512u;

    int e  = __ldg(&g_row_ptr[warp]);
    int e1 = __ldg(&g_row_ptr[warp + 1]);

    float4 acc0 = make_float4(0.f, 0.f, 0.f, 0.f);
    float4 acc1 = make_float4(0.f, 0.f, 0.f, 0.f);

    Pend PA, PB;
    bool haveA = false, haveB = false;
    int  ep = e;
    if (ep + 2 <= e1) { PA = stage_pair(src, affine, ep, slotA, lane); cp_commit(); ep += 2; haveA = true; }
    if (ep + 2 <= e1) { PB = stage_pair(src, affine, ep, slotB, lane); cp_commit(); ep += 2; haveB = true; }

    while (haveA) {
        // consume A
        if (haveB) cp_wait<1>(); else cp_wait<0>();
        __syncwarp();
        acc_lds(acc0, slotA +   0 + off_in_slot(PA.s0, lane), PA.a0);
        acc_lds(acc1, slotA + 256 + off_in_slot(PA.s1, lane), PA.a1);
        __syncwarp();
        haveA = false;
        if (ep + 2 <= e1) { PA = stage_pair(src, affine, ep, slotA, lane); cp_commit(); ep += 2; haveA = true; }

        if (!haveB) break;
        // consume B
        if (haveA) cp_wait<1>(); else cp_wait<0>();
        __syncwarp();
        acc_lds(acc0, slotB +   0 + off_in_slot(PB.s0, lane), PB.a0);
        acc_lds(acc1, slotB + 256 + off_in_slot(PB.s1, lane), PB.a1);
        __syncwarp();
        haveB = false;
        if (ep + 2 <= e1) { PB = stage_pair(src, affine, ep, slotB, lane); cp_commit(); ep += 2; haveB = true; }
    }

    // remainder (0 or 1 edge)
    for (; ep < e1; ++ep) {
        int   s = __ldg(src + ep);
        float a = __ldg(affine + ep);
        acc_gmem(acc0, s, a, lane);
    }

    float4 r = make_float4(acc0.x + acc1.x, acc0.y + acc1.y,
                           acc0.z + acc1.z, acc0.w + acc1.w);

    int b   = warp >> 7;
    int row = warp & 127;
    int t   = lane >> 4;             // -> kt 2/3
    uint32_t off  = SWZ128((uint32_t)(row * 128 + (lane & 15) * 8));
    size_t   base = ((size_t)b * 4 + 2 + t) * TILE_B;
    *reinterpret_cast<uint2*>(g_xh_img + base + off) = hi4(r);
}

// ===========================================================================
// Kernel 3: pure-streaming 2-pass fp16 HMMA GEMM (R9 version — best measured).
// ===========================================================================
#define STAGE_B   49152u
#define SM_TOTAL  (4 * 49152)     // 196608

__device__ __forceinline__ void mma_tile32(
    uint32_t xh, uint32_t wh, uint32_t wl,
    float c[2][4][4], int lane, int wm, int wn)
{
#pragma unroll
    for (int ks = 0; ks < 4; ++ks) {
        uint32_t ah[2][4];
#pragma unroll
        for (int t = 0; t < 2; ++t) {
            int row = wm * 32 + t * 16 + (lane & 15);
            uint32_t off = SWZ128((uint32_t)(row * 128 + ks * 32 + (lane >> 4) * 16));
            ldsm_x4(ah[t], xh + off);
        }
        int bg    = lane >> 3;
        int bn_in = ((bg >> 1) << 3) + (lane & 7);
        int bk    = ks * 32 + (bg & 1) * 16;

        uint32_t bh[2][4], bl[2][4];
#pragma unroll
        for (int j = 0; j < 2; ++j) {
            int n = wn * 32 + j * 16 + bn_in;
            uint32_t noff = SWZ128((uint32_t)(n * 128 + bk));
            ldsm_x4(bh[j], wh + noff);
            ldsm_x4(bl[j], wl + noff);
        }
#pragma unroll
        for (int t = 0; t < 2; ++t)
#pragma unroll
            for (int j = 0; j < 2; ++j) {
                mma_f16(c[t][2 * j + 0], ah[t], bh[j][0], bh[j][1]);
                mma_f16(c[t][2 * j + 1], ah[t], bh[j][2], bh[j][3]);
                mma_f16(c[t][2 * j + 0], ah[t], bl[j][0], bl[j][1]);
                mma_f16(c[t][2 * j + 1], ah[t], bl[j][2], bl[j][3]);
            }
    }
}

__global__ __launch_bounds__(512) void gemm_kernel(
    const float* __restrict__ bias,
    float*       __restrict__ out,
    int M)
{
    extern __shared__ char smem[];
    const uint32_t sb = smem_u32(smem);
    const int tid  = threadIdx.x;
    const int lane = tid & 31;
    const int wid  = tid >> 5;
    const int wm   = wid >> 2;
    const int wn   = wid & 3;
    const int m0   = blockIdx.x * MT;
    const int b    = blockIdx.x;

#pragma unroll
    for (int kt = 0; kt < 4; ++kt) {
        size_t xb = ((size_t)b * 4 + kt) * TILE_B;
        size_t wb = (size_t)kt * TILE_B;
#pragma unroll
        for (int j = 0; j < 2; ++j) {
            uint32_t o = (uint32_t)(j * 512 + tid) * 16;
            cp_async16(sb + kt * STAGE_B + o,          g_xh_img + xb + o);
            cp_async16(sb + kt * STAGE_B + 16384 + o,  g_Wh_img + wb + o);
            cp_async16(sb + kt * STAGE_B + 32768 + o,  g_Wl_img + wb + o);
        }
        cp_commit();
    }

    float c[2][4][4];
#pragma unroll
    for (int t = 0; t < 2; ++t)
#pragma unroll
        for (int j = 0; j < 4; ++j)
#pragma unroll
            for (int q = 0; q < 4; ++q) c[t][j][q] = 0.f;

    cp_wait<3>(); __syncthreads();
    mma_tile32(sb + 0 * STAGE_B, sb + 0 * STAGE_B + 16384, sb + 0 * STAGE_B + 32768,
               c, lane, wm, wn);
    cp_wait<2>(); __syncthreads();
    mma_tile32(sb + 1 * STAGE_B, sb + 1 * STAGE_B + 16384, sb + 1 * STAGE_B + 32768,
               c, lane, wm, wn);
    cp_wait<1>(); __syncthreads();
    mma_tile32(sb + 2 * STAGE_B, sb + 2 * STAGE_B + 16384, sb + 2 * STAGE_B + 32768,
               c, lane, wm, wn);
    cp_wait<0>(); __syncthreads();
    mma_tile32(sb + 3 * STAGE_B, sb + 3 * STAGE_B + 16384, sb + 3 * STAGE_B + 32768,
               c, lane, wm, wn);

    // ---- epilogue: bias + store ----
#pragma unroll
    for (int t = 0; t < 2; ++t) {
#pragma unroll
        for (int j = 0; j < 4; ++j) {
            int col = wn * 32 + (j >> 1) * 16 + (j & 1) * 8 + (lane & 3) * 2;
            float b0 = __ldg(bias + col);
            float b1 = __ldg(bias + col + 1);
            int r0 = m0 + wm * 32 + t * 16 + (lane >> 2);
            int r1 = r0 + 8;
            if (r0 < M) {
                float2 o = make_float2(c[t][j][0] + b0, c[t][j][1] + b1);
                *reinterpret_cast<float2*>(out + (size_t)r0 * D_FEAT + col) = o;
            }
            if (r1 < M) {
                float2 o = make_float2(c[t][j][2] + b0, c[t][j][3] + b1);
                *reinterpret_cast<float2*>(out + (size_t)r1 * D_FEAT + col) = o;
            }
        }
    }
}

// ===========================================================================
// Launch
// ===========================================================================
extern "C" void kernel_launch(void* const* d_in, const int* in_sizes, int n_in,
                              void* d_out, int out_size)
{
    const float* feat   = (const float*)d_in[0];
    const float* affine = (const float*)d_in[1];
    const int*   src    = (const int*)  d_in[2];
    const int*   dst    = (const int*)  d_in[3];
    const float* W      = (const float*)d_in[4];
    const float* bias   = (const float*)d_in[5];
    float*       out    = (float*)d_out;

    const int n_nodes = in_sizes[0] / D_FEAT;
    const int n_edges = in_sizes[1];

    cudaFuncSetAttribute(gemm_kernel,
                         cudaFuncAttributeMaxDynamicSharedMemorySize, SM_TOTAL);

    int rpb = ((n_edges + 3) / 4 + 255) / 256;     // rowptr blocks
    int fpb = (n_nodes * 16 + 1023) / 1024;        // featprep blocks
    prep1_kernel<<<rpb + fpb + 16, 256>>>(
        reinterpret_cast<const float4*>(feat), dst, W,
        n_nodes, n_edges, rpb, fpb);

    agg_kernel<<<(n_nodes * 32 + 255) / 256, 256>>>(affine, src, n_nodes);

    gemm_kernel<<<(n_nodes + MT - 1) / MT, 512, SM_TOTAL>>>(bias, out, n_nodes);
}

// round 16
// speedup vs baseline: 1.1176x; 1.1176x over previous
#include <cuda_runtime.h>
#include <cuda_fp16.h>
#include <cstdint>

// Problem constants
#define N_NODES 50000
#define D_FEAT  128
#define K_TOT   256
#define MT      128
#define NCTA    ((N_NODES + MT - 1) / MT)   // 391
#define TILE_B  16384                        // one [128 x 64] fp16 tile image

// X tile images (fp16): per gemm-CTA b, kt0/1 = feat, kt2/3 = agg.
__device__ __align__(16) uint8_t g_xh_img[(size_t)NCTA * 4 * TILE_B];
__device__ __align__(16) uint8_t g_Wh_img[4 * TILE_B];
__device__ __align__(16) uint8_t g_Wl_img[4 * TILE_B];
__device__ int g_row_ptr[N_NODES + 1];

// ===========================================================================
// Helpers
// ===========================================================================
__device__ __forceinline__ uint32_t smem_u32(const void* p) {
    uint32_t a;
    asm("{ .reg .u64 t; cvta.to.shared.u64 t, %1; cvt.u32.u64 %0, t; }"
        : "=r"(a) : "l"(p));
    return a;
}
#define SWZ128(off) ((off) ^ (((off) >> 3) & 0x70))

__device__ __forceinline__ uint32_t pack_h2(float a, float b) {
    __half2 h = __floats2half2_rn(a, b);
    return *reinterpret_cast<uint32_t*>(&h);
}
__device__ __forceinline__ void ldsm_x4(uint32_t r[4], uint32_t addr) {
    asm volatile("ldmatrix.sync.aligned.m8n8.x4.shared.b16 {%0,%1,%2,%3}, [%4];"
                 : "=r"(r[0]), "=r"(r[1]), "=r"(r[2]), "=r"(r[3]) : "r"(addr));
}
__device__ __forceinline__ void mma_f16(float c[4], const uint32_t a[4],
                                        uint32_t b0, uint32_t b1) {
    asm volatile(
        "mma.sync.aligned.m16n8k16.row.col.f32.f16.f16.f32 "
        "{%0,%1,%2,%3}, {%4,%5,%6,%7}, {%8,%9}, {%0,%1,%2,%3};"
        : "+f"(c[0]), "+f"(c[1]), "+f"(c[2]), "+f"(c[3])
        : "r"(a[0]), "r"(a[1]), "r"(a[2]), "r"(a[3]), "r"(b0), "r"(b1));
}
__device__ __forceinline__ void cp_async16(uint32_t smem, const void* gmem) {
    asm volatile("cp.async.cg.shared.global [%0], [%1], 16;\n"
                 :: "r"(smem), "l"(gmem));
}
__device__ __forceinline__ void cp_commit() {
    asm volatile("cp.async.commit_group;\n" ::);
}
template <int N>
__device__ __forceinline__ void cp_wait() {
    asm volatile("cp.async.wait_group %0;\n" :: "n"(N));
}
__device__ __forceinline__ uint2 hi4(float4 v) {
    return make_uint2(pack_h2(v.x, v.y), pack_h2(v.z, v.w));
}

// ===========================================================================
// Kernel 1 (fused, independent parts): rowptr | featprep | wprep
// (R14 version)
// ===========================================================================
__global__ __launch_bounds__(256) void prep1_kernel(
    const float4* __restrict__ feat4,
    const int*    __restrict__ dst,
    const float*  __restrict__ W,
    int n_nodes, int n_edges, int rpb, int fpb)
{
    const int bid = blockIdx.x;
    const int tid = threadIdx.x;

    if (bid < rpb) {
        // ---- rowptr: 4 edges per thread ----
        int e4 = bid * 256 + tid;
        int e0 = e4 * 4;
        if (e0 >= n_edges) return;
        int v0, v1, v2, v3;
        if (e0 + 3 < n_edges) {
            int4 d = __ldg(reinterpret_cast<const int4*>(dst) + e4);
            v0 = d.x; v1 = d.y; v2 = d.z; v3 = d.w;
        } else {
            v0 = __ldg(dst + e0);
            v1 = (e0 + 1 < n_edges) ? __ldg(dst + e0 + 1) : v0;
            v2 = (e0 + 2 < n_edges) ? __ldg(dst + e0 + 2) : v1;
            v3 = (e0 + 3 < n_edges) ? __ldg(dst + e0 + 3) : v2;
        }
        int dp = (e0 == 0) ? -1 : __ldg(dst + e0 - 1);
        int vals[5] = {dp, v0, v1, v2, v3};
#pragma unroll
        for (int j = 0; j < 4; ++j)
            if (e0 + j < n_edges)
                for (int v = vals[j] + 1; v <= vals[j + 1]; ++v)
                    g_row_ptr[v] = e0 + j;
        if (e0 + 4 >= n_edges) {
            int last = vals[4 - (e0 + 4 - n_edges)];
            for (int v = last + 1; v <= n_nodes; ++v) g_row_ptr[v] = n_edges;
        }
    } else if (bid < rpb + fpb) {
        // ---- featprep: thread owns (node v, 8 k's) -> one 16B store ----
        int base  = (bid - rpb) * 1024 + tid;
        int total = n_nodes * 16;
#pragma unroll
        for (int i = 0; i < 4; ++i) {
            int idx = base + i * 256;
            if (idx < total) {
                int v  = idx >> 4;
                int c8 = idx & 15;          // 8-k group
                float4 f0 = __ldg(feat4 + (size_t)v * 32 + c8 * 2);
                float4 f1 = __ldg(feat4 + (size_t)v * 32 + c8 * 2 + 1);
                uint2 h0 = hi4(f0), h1 = hi4(f1);
                int b   = v >> 7;
                int row = v & 127;
                int t   = c8 >> 3;          // tile kt0/1
                uint32_t off = SWZ128((uint32_t)(row * 128 + (c8 & 7) * 16));
                uint4 val = make_uint4(h0.x, h0.y, h1.x, h1.y);
                *reinterpret_cast<uint4*>(
                    g_xh_img + ((size_t)b * 4 + t) * TILE_B + off) = val;
            }
        }
    } else {
        // ---- wprep: fp16 hi/lo ----
        for (int idx = (bid - rpb - fpb) * 256 + tid; idx < K_TOT * D_FEAT;
             idx += 16 * 256) {
            int n = idx & 127;
            int k = idx >> 7;
            float w = __ldg(W + (size_t)k * D_FEAT + n);
            __half h = __float2half(w);
            __half l = __float2half(w - __half2float(h));
            int kt = k >> 6;
            int kc = k & 63;
            uint32_t off = SWZ128((uint32_t)(n * 128 + kc * 2));
            *reinterpret_cast<__half*>(g_Wh_img + kt * TILE_B + off) = h;
            *reinterpret_cast<__half*>(g_Wl_img + kt * TILE_B + off) = l;
        }
    }
}

// ===========================================================================
// Kernel 2: warp-per-node segmented reduction, EDGE-PAIR layout:
// lanes 0-15 own edge i, lanes 16-31 own edge i+1; each lane loads 16B
// (LDG.128, 8 fp16 k-values) -> half the gather instructions per edge.
// Final shfl_xor(16) reduction; lanes 0-15 store one uint4 into kt2/3.
// ===========================================================================
__device__ __forceinline__ void acc8(float4& x, float4& y, uint4 d, float a) {
    float2 f;
    f = __half22float2(*reinterpret_cast<const __half2*>(&d.x));
    x.x = fmaf(f.x, a, x.x); x.y = fmaf(f.y, a, x.y);
    f = __half22float2(*reinterpret_cast<const __half2*>(&d.y));
    x.z = fmaf(f.x, a, x.z); x.w = fmaf(f.y, a, x.w);
    f = __half22float2(*reinterpret_cast<const __half2*>(&d.z));
    y.x = fmaf(f.x, a, y.x); y.y = fmaf(f.y, a, y.y);
    f = __half22float2(*reinterpret_cast<const __half2*>(&d.w));
    y.z = fmaf(f.x, a, y.z); y.w = fmaf(f.y, a, y.w);
}

// address of 16B chunk (li&7)*16 in tile (li>>3) of source node s's row
__device__ __forceinline__ const uint4* grow16(int s, int li) {
    const uint8_t* p = g_xh_img
        + ((size_t)(s >> 7) * 4 + (uint32_t)(li >> 3)) * TILE_B
        + (uint32_t)(s & 127) * 128
        + (((uint32_t)(li & 7) * 16) ^ (((uint32_t)s & 7) << 4));
    return reinterpret_cast<const uint4*>(p);
}

__global__ __launch_bounds__(256) void agg_kernel(
    const float* __restrict__ affine,
    const int*   __restrict__ src,
    int n_nodes)
{
    int warp = (blockIdx.x * blockDim.x + threadIdx.x) >> 5;
    int lane = threadIdx.x & 31;
    if (warp >= n_nodes) return;

    const int el = lane >> 4;        // edge slot within pair (0/1)
    const int li = lane & 15;        // 16B chunk owner (k = li*8 .. li*8+7)

    int e  = __ldg(&g_row_ptr[warp]);
    int e1 = __ldg(&g_row_ptr[warp + 1]);

    float4 ax0 = make_float4(0.f, 0.f, 0.f, 0.f);
    float4 ay0 = make_float4(0.f, 0.f, 0.f, 0.f);
    float4 ax1 = make_float4(0.f, 0.f, 0.f, 0.f);
    float4 ay1 = make_float4(0.f, 0.f, 0.f, 0.f);

    // main loop: 4 edges per iteration, 2 independent 16B gathers per lane
    for (; e + 4 <= e1; e += 4) {
        int   s0 = __ldg(src + e + el);
        int   s1 = __ldg(src + e + 2 + el);
        float a0 = __ldg(affine + e + el);
        float a1 = __ldg(affine + e + 2 + el);
        uint4 d0 = __ldg(grow16(s0, li));
        uint4 d1 = __ldg(grow16(s1, li));
        acc8(ax0, ay0, d0, a0);
        acc8(ax1, ay1, d1, a1);
    }
    // leftover pair
    if (e + 2 <= e1) {
        int   s = __ldg(src + e + el);
        float a = __ldg(affine + e + el);
        uint4 d = __ldg(grow16(s, li));
        acc8(ax0, ay0, d, a);
        e += 2;
    }
    // leftover single edge: both halves load same row, el=1 uses a=0
    if (e < e1) {
        int   s = __ldg(src + e);
        float a = (el == 0) ? __ldg(affine + e) : 0.f;
        uint4 d = __ldg(grow16(s, li));
        acc8(ax0, ay0, d, a);
    }

    float4 x = make_float4(ax0.x + ax1.x, ax0.y + ax1.y,
                           ax0.z + ax1.z, ax0.w + ax1.w);
    float4 y = make_float4(ay0.x + ay1.x, ay0.y + ay1.y,
                           ay0.z + ay1.z, ay0.w + ay1.w);

    // reduce across the two edge slots (lane L <-> L+16)
    x.x += __shfl_xor_sync(0xffffffffu, x.x, 16);
    x.y += __shfl_xor_sync(0xffffffffu, x.y, 16);
    x.z += __shfl_xor_sync(0xffffffffu, x.z, 16);
    x.w += __shfl_xor_sync(0xffffffffu, x.w, 16);
    y.x += __shfl_xor_sync(0xffffffffu, y.x, 16);
    y.y += __shfl_xor_sync(0xffffffffu, y.y, 16);
    y.z += __shfl_xor_sync(0xffffffffu, y.z, 16);
    y.w += __shfl_xor_sync(0xffffffffu, y.w, 16);

    if (el == 0) {
        uint4 val = make_uint4(pack_h2(x.x, x.y), pack_h2(x.z, x.w),
                               pack_h2(y.x, y.y), pack_h2(y.z, y.w));
        int b   = warp >> 7;
        int row = warp & 127;
        int t   = li >> 3;           // -> kt 2/3
        uint32_t off  = SWZ128((uint32_t)(row * 128 + (li & 7) * 16));
        size_t   base = ((size_t)b * 4 + 2 + t) * TILE_B;
        *reinterpret_cast<uint4*>(g_xh_img + base + off) = val;
    }
}

// ===========================================================================
// Kernel 3: pure-streaming 2-pass fp16 HMMA GEMM (R9/R14 version).
// ===========================================================================
#define STAGE_B   49152u
#define SM_TOTAL  (4 * 49152)     // 196608

__device__ __forceinline__ void mma_tile32(
    uint32_t xh, uint32_t wh, uint32_t wl,
    float c[2][4][4], int lane, int wm, int wn)
{
#pragma unroll
    for (int ks = 0; ks < 4; ++ks) {
        uint32_t ah[2][4];
#pragma unroll
        for (int t = 0; t < 2; ++t) {
            int row = wm * 32 + t * 16 + (lane & 15);
            uint32_t off = SWZ128((uint32_t)(row * 128 + ks * 32 + (lane >> 4) * 16));
            ldsm_x4(ah[t], xh + off);
        }
        int bg    = lane >> 3;
        int bn_in = ((bg >> 1) << 3) + (lane & 7);
        int bk    = ks * 32 + (bg & 1) * 16;

        uint32_t bh[2][4], bl[2][4];
#pragma unroll
        for (int j = 0; j < 2; ++j) {
            int n = wn * 32 + j * 16 + bn_in;
            uint32_t noff = SWZ128((uint32_t)(n * 128 + bk));
            ldsm_x4(bh[j], wh + noff);
            ldsm_x4(bl[j], wl + noff);
        }
#pragma unroll
        for (int t = 0; t < 2; ++t)
#pragma unroll
            for (int j = 0; j < 2; ++j) {
                mma_f16(c[t][2 * j + 0], ah[t], bh[j][0], bh[j][1]);
                mma_f16(c[t][2 * j + 1], ah[t], bh[j][2], bh[j][3]);
                mma_f16(c[t][2 * j + 0], ah[t], bl[j][0], bl[j][1]);
                mma_f16(c[t][2 * j + 1], ah[t], bl[j][2], bl[j][3]);
            }
    }
}

__global__ __launch_bounds__(512) void gemm_kernel(
    const float* __restrict__ bias,
    float*       __restrict__ out,
    int M)
{
    extern __shared__ char smem[];
    const uint32_t sb = smem_u32(smem);
    const int tid  = threadIdx.x;
    const int lane = tid & 31;
    const int wid  = tid >> 5;
    const int wm   = wid >> 2;
    const int wn   = wid & 3;
    const int m0   = blockIdx.x * MT;
    const int b    = blockIdx.x;

#pragma unroll
    for (int kt = 0; kt < 4; ++kt) {
        size_t xb = ((size_t)b * 4 + kt) * TILE_B;
        size_t wb = (size_t)kt * TILE_B;
#pragma unroll
        for (int j = 0; j < 2; ++j) {
            uint32_t o = (uint32_t)(j * 512 + tid) * 16;
            cp_async16(sb + kt * STAGE_B + o,          g_xh_img + xb + o);
            cp_async16(sb + kt * STAGE_B + 16384 + o,  g_Wh_img + wb + o);
            cp_async16(sb + kt * STAGE_B + 32768 + o,  g_Wl_img + wb + o);
        }
        cp_commit();
    }

    float c[2][4][4];
#pragma unroll
    for (int t = 0; t < 2; ++t)
#pragma unroll
        for (int j = 0; j < 4; ++j)
#pragma unroll
            for (int q = 0; q < 4; ++q) c[t][j][q] = 0.f;

    cp_wait<3>(); __syncthreads();
    mma_tile32(sb + 0 * STAGE_B, sb + 0 * STAGE_B + 16384, sb + 0 * STAGE_B + 32768,
               c, lane, wm, wn);
    cp_wait<2>(); __syncthreads();
    mma_tile32(sb + 1 * STAGE_B, sb + 1 * STAGE_B + 16384, sb + 1 * STAGE_B + 32768,
               c, lane, wm, wn);
    cp_wait<1>(); __syncthreads();
    mma_tile32(sb + 2 * STAGE_B, sb + 2 * STAGE_B + 16384, sb + 2 * STAGE_B + 32768,
               c, lane, wm, wn);
    cp_wait<0>(); __syncthreads();
    mma_tile32(sb + 3 * STAGE_B, sb + 3 * STAGE_B + 16384, sb + 3 * STAGE_B + 32768,
               c, lane, wm, wn);

    // ---- epilogue: bias + store ----
#pragma unroll
    for (int t = 0; t < 2; ++t) {
#pragma unroll
        for (int j = 0; j < 4; ++j) {
            int col = wn * 32 + (j >> 1) * 16 + (j & 1) * 8 + (lane & 3) * 2;
            float b0 = __ldg(bias + col);
            float b1 = __ldg(bias + col + 1);
            int r0 = m0 + wm * 32 + t * 16 + (lane >> 2);
            int r1 = r0 + 8;
            if (r0 < M) {
                float2 o = make_float2(c[t][j][0] + b0, c[t][j][1] + b1);
                *reinterpret_cast<float2*>(out + (size_t)r0 * D_FEAT + col) = o;
            }
            if (r1 < M) {
                float2 o = make_float2(c[t][j][2] + b0, c[t][j][3] + b1);
                *reinterpret_cast<float2*>(out + (size_t)r1 * D_FEAT + col) = o;
            }
        }
    }
}

// ===========================================================================
// Launch
// ===========================================================================
extern "C" void kernel_launch(void* const* d_in, const int* in_sizes, int n_in,
                              void* d_out, int out_size)
{
    const float* feat   = (const float*)d_in[0];
    const float* affine = (const float*)d_in[1];
    const int*   src    = (const int*)  d_in[2];
    const int*   dst    = (const int*)  d_in[3];
    const float* W      = (const float*)d_in[4];
    const float* bias   = (const float*)d_in[5];
    float*       out    = (float*)d_out;

    const int n_nodes = in_sizes[0] / D_FEAT;
    const int n_edges = in_sizes[1];

    cudaFuncSetAttribute(gemm_kernel,
                         cudaFuncAttributeMaxDynamicSharedMemorySize, SM_TOTAL);

    int rpb = ((n_edges + 3) / 4 + 255) / 256;     // rowptr blocks
    int fpb = (n_nodes * 16 + 1023) / 1024;        // featprep blocks
    prep1_kernel<<<rpb + fpb + 16, 256>>>(
        reinterpret_cast<const float4*>(feat), dst, W,
        n_nodes, n_edges, rpb, fpb);

    agg_kernel<<<(n_nodes * 32 + 255) / 256, 256>>>(affine, src, n_nodes);

    gemm_kernel<<<(n_nodes + MT - 1) / MT, 512, SM_TOTAL>>>(bias, out, n_nodes);
}

// round 17
// speedup vs baseline: 1.1635x; 1.0410x over previous
#include <cuda_runtime.h>
#include <cuda_fp16.h>
#include <cstdint>

// Problem constants
#define N_NODES 50000
#define D_FEAT  128
#define K_TOT   256
#define MT      128
#define NCTA    ((N_NODES + MT - 1) / MT)   // 391
#define TILE_B  16384                        // one [128 x 64] fp16 tile image

// X tile images (fp16): per gemm-CTA b, kt0/1 = feat, kt2/3 = agg.
__device__ __align__(16) uint8_t g_xh_img[(size_t)NCTA * 4 * TILE_B];
__device__ __align__(16) uint8_t g_Wh_img[4 * TILE_B];
__device__ __align__(16) uint8_t g_Wl_img[4 * TILE_B];
__device__ int g_row_ptr[N_NODES + 1];

// ===========================================================================
// Helpers
// ===========================================================================
__device__ __forceinline__ uint32_t smem_u32(const void* p) {
    uint32_t a;
    asm("{ .reg .u64 t; cvta.to.shared.u64 t, %1; cvt.u32.u64 %0, t; }"
        : "=r"(a) : "l"(p));
    return a;
}
#define SWZ128(off) ((off) ^ (((off) >> 3) & 0x70))

__device__ __forceinline__ uint32_t pack_h2(float a, float b) {
    __half2 h = __floats2half2_rn(a, b);
    return *reinterpret_cast<uint32_t*>(&h);
}
__device__ __forceinline__ void ldsm_x4(uint32_t r[4], uint32_t addr) {
    asm volatile("ldmatrix.sync.aligned.m8n8.x4.shared.b16 {%0,%1,%2,%3}, [%4];"
                 : "=r"(r[0]), "=r"(r[1]), "=r"(r[2]), "=r"(r[3]) : "r"(addr));
}
__device__ __forceinline__ void mma_f16(float c[4], const uint32_t a[4],
                                        uint32_t b0, uint32_t b1) {
    asm volatile(
        "mma.sync.aligned.m16n8k16.row.col.f32.f16.f16.f32 "
        "{%0,%1,%2,%3}, {%4,%5,%6,%7}, {%8,%9}, {%0,%1,%2,%3};"
        : "+f"(c[0]), "+f"(c[1]), "+f"(c[2]), "+f"(c[3])
        : "r"(a[0]), "r"(a[1]), "r"(a[2]), "r"(a[3]), "r"(b0), "r"(b1));
}
__device__ __forceinline__ void cp_async16(uint32_t smem, const void* gmem) {
    asm volatile("cp.async.cg.shared.global [%0], [%1], 16;\n"
                 :: "r"(smem), "l"(gmem));
}
__device__ __forceinline__ void cp_commit() {
    asm volatile("cp.async.commit_group;\n" ::);
}
template <int N>
__device__ __forceinline__ void cp_wait() {
    asm volatile("cp.async.wait_group %0;\n" :: "n"(N));
}
__device__ __forceinline__ uint2 hi4(float4 v) {
    return make_uint2(pack_h2(v.x, v.y), pack_h2(v.z, v.w));
}

// ===========================================================================
// Kernel 1 (fused, independent parts): rowptr | featprep | wprep
// featprep: ONE element per thread (no loop) -> max thread-level MLP.
// ===========================================================================
__global__ __launch_bounds__(256) void prep1_kernel(
    const float4* __restrict__ feat4,
    const int*    __restrict__ dst,
    const float*  __restrict__ W,
    int n_nodes, int n_edges, int rpb, int fpb)
{
    const int bid = blockIdx.x;
    const int tid = threadIdx.x;

    if (bid < rpb) {
        // ---- rowptr: 4 edges per thread ----
        int e4 = bid * 256 + tid;
        int e0 = e4 * 4;
        if (e0 >= n_edges) return;
        int v0, v1, v2, v3;
        if (e0 + 3 < n_edges) {
            int4 d = __ldg(reinterpret_cast<const int4*>(dst) + e4);
            v0 = d.x; v1 = d.y; v2 = d.z; v3 = d.w;
        } else {
            v0 = __ldg(dst + e0);
            v1 = (e0 + 1 < n_edges) ? __ldg(dst + e0 + 1) : v0;
            v2 = (e0 + 2 < n_edges) ? __ldg(dst + e0 + 2) : v1;
            v3 = (e0 + 3 < n_edges) ? __ldg(dst + e0 + 3) : v2;
        }
        int dp = (e0 == 0) ? -1 : __ldg(dst + e0 - 1);
        int vals[5] = {dp, v0, v1, v2, v3};
#pragma unroll
        for (int j = 0; j < 4; ++j)
            if (e0 + j < n_edges)
                for (int v = vals[j] + 1; v <= vals[j + 1]; ++v)
                    g_row_ptr[v] = e0 + j;
        if (e0 + 4 >= n_edges) {
            int last = vals[4 - (e0 + 4 - n_edges)];
            for (int v = last + 1; v <= n_nodes; ++v) g_row_ptr[v] = n_edges;
        }
    } else if (bid < rpb + fpb) {
        // ---- featprep: thread owns (node v, 8 k's); 2 LDG.128 + 1 STG.128 ----
        int idx = (bid - rpb) * 256 + tid;
        if (idx < n_nodes * 16) {
            int v  = idx >> 4;
            int c8 = idx & 15;              // 8-k group
            float4 f0 = __ldg(feat4 + (size_t)v * 32 + c8 * 2);
            float4 f1 = __ldg(feat4 + (size_t)v * 32 + c8 * 2 + 1);
            uint2 h0 = hi4(f0), h1 = hi4(f1);
            int b   = v >> 7;
            int row = v & 127;
            int t   = c8 >> 3;              // tile kt0/1
            uint32_t off = SWZ128((uint32_t)(row * 128 + (c8 & 7) * 16));
            uint4 val = make_uint4(h0.x, h0.y, h1.x, h1.y);
            *reinterpret_cast<uint4*>(
                g_xh_img + ((size_t)b * 4 + t) * TILE_B + off) = val;
        }
    } else {
        // ---- wprep: fp16 hi/lo ----
        for (int idx = (bid - rpb - fpb) * 256 + tid; idx < K_TOT * D_FEAT;
             idx += 16 * 256) {
            int n = idx & 127;
            int k = idx >> 7;
            float w = __ldg(W + (size_t)k * D_FEAT + n);
            __half h = __float2half(w);
            __half l = __float2half(w - __half2float(h));
            int kt = k >> 6;
            int kc = k & 63;
            uint32_t off = SWZ128((uint32_t)(n * 128 + kc * 2));
            *reinterpret_cast<__half*>(g_Wh_img + kt * TILE_B + off) = h;
            *reinterpret_cast<__half*>(g_Wl_img + kt * TILE_B + off) = l;
        }
    }
}

// ===========================================================================
// Kernel 2: warp-per-node segmented reduction, EDGE-PAIR layout (R16 —
// measured win): lanes 0-15 own edge i, lanes 16-31 own edge i+1; each lane
// one LDG.128 (8 fp16 k). Final shfl_xor(16); lanes 0-15 store one uint4.
// ===========================================================================
__device__ __forceinline__ void acc8(float4& x, float4& y, uint4 d, float a) {
    float2 f;
    f = __half22float2(*reinterpret_cast<const __half2*>(&d.x));
    x.x = fmaf(f.x, a, x.x); x.y = fmaf(f.y, a, x.y);
    f = __half22float2(*reinterpret_cast<const __half2*>(&d.y));
    x.z = fmaf(f.x, a, x.z); x.w = fmaf(f.y, a, x.w);
    f = __half22float2(*reinterpret_cast<const __half2*>(&d.z));
    y.x = fmaf(f.x, a, y.x); y.y = fmaf(f.y, a, y.y);
    f = __half22float2(*reinterpret_cast<const __half2*>(&d.w));
    y.z = fmaf(f.x, a, y.z); y.w = fmaf(f.y, a, y.w);
}

__device__ __forceinline__ const uint4* grow16(int s, int li) {
    const uint8_t* p = g_xh_img
        + ((size_t)(s >> 7) * 4 + (uint32_t)(li >> 3)) * TILE_B
        + (uint32_t)(s & 127) * 128
        + (((uint32_t)(li & 7) * 16) ^ (((uint32_t)s & 7) << 4));
    return reinterpret_cast<const uint4*>(p);
}

__global__ __launch_bounds__(256) void agg_kernel(
    const float* __restrict__ affine,
    const int*   __restrict__ src,
    int n_nodes)
{
    int warp = (blockIdx.x * blockDim.x + threadIdx.x) >> 5;
    int lane = threadIdx.x & 31;
    if (warp >= n_nodes) return;

    const int el = lane >> 4;        // edge slot within pair (0/1)
    const int li = lane & 15;        // 16B chunk owner (k = li*8 .. li*8+7)

    int e  = __ldg(&g_row_ptr[warp]);
    int e1 = __ldg(&g_row_ptr[warp + 1]);

    float4 ax0 = make_float4(0.f, 0.f, 0.f, 0.f);
    float4 ay0 = make_float4(0.f, 0.f, 0.f, 0.f);
    float4 ax1 = make_float4(0.f, 0.f, 0.f, 0.f);
    float4 ay1 = make_float4(0.f, 0.f, 0.f, 0.f);

    for (; e + 4 <= e1; e += 4) {
        int   s0 = __ldg(src + e + el);
        int   s1 = __ldg(src + e + 2 + el);
        float a0 = __ldg(affine + e + el);
        float a1 = __ldg(affine + e + 2 + el);
        uint4 d0 = __ldg(grow16(s0, li));
        uint4 d1 = __ldg(grow16(s1, li));
        acc8(ax0, ay0, d0, a0);
        acc8(ax1, ay1, d1, a1);
    }
    if (e + 2 <= e1) {
        int   s = __ldg(src + e + el);
        float a = __ldg(affine + e + el);
        uint4 d = __ldg(grow16(s, li));
        acc8(ax0, ay0, d, a);
        e += 2;
    }
    if (e < e1) {
        int   s = __ldg(src + e);
        float a = (el == 0) ? __ldg(affine + e) : 0.f;
        uint4 d = __ldg(grow16(s, li));
        acc8(ax0, ay0, d, a);
    }

    float4 x = make_float4(ax0.x + ax1.x, ax0.y + ax1.y,
                           ax0.z + ax1.z, ax0.w + ax1.w);
    float4 y = make_float4(ay0.x + ay1.x, ay0.y + ay1.y,
                           ay0.z + ay1.z, ay0.w + ay1.w);

    x.x += __shfl_xor_sync(0xffffffffu, x.x, 16);
    x.y += __shfl_xor_sync(0xffffffffu, x.y, 16);
    x.z += __shfl_xor_sync(0xffffffffu, x.z, 16);
    x.w += __shfl_xor_sync(0xffffffffu, x.w, 16);
    y.x += __shfl_xor_sync(0xffffffffu, y.x, 16);
    y.y += __shfl_xor_sync(0xffffffffu, y.y, 16);
    y.z += __shfl_xor_sync(0xffffffffu, y.z, 16);
    y.w += __shfl_xor_sync(0xffffffffu, y.w, 16);

    if (el == 0) {
        uint4 val = make_uint4(pack_h2(x.x, x.y), pack_h2(x.z, x.w),
                               pack_h2(y.x, y.y), pack_h2(y.z, y.w));
        int b   = warp >> 7;
        int row = warp & 127;
        int t   = li >> 3;           // -> kt 2/3
        uint32_t off  = SWZ128((uint32_t)(row * 128 + (li & 7) * 16));
        size_t   base = ((size_t)b * 4 + 2 + t) * TILE_B;
        *reinterpret_cast<uint4*>(g_xh_img + base + off) = val;
    }
}

// ===========================================================================
// Kernel 3: pure-streaming 2-pass fp16 HMMA GEMM (R9/R14 version).
// ===========================================================================
#define STAGE_B   49152u
#define SM_TOTAL  (4 * 49152)     // 196608

__device__ __forceinline__ void mma_tile32(
    uint32_t xh, uint32_t wh, uint32_t wl,
    float c[2][4][4], int lane, int wm, int wn)
{
#pragma unroll
    for (int ks = 0; ks < 4; ++ks) {
        uint32_t ah[2][4];
#pragma unroll
        for (int t = 0; t < 2; ++t) {
            int row = wm * 32 + t * 16 + (lane & 15);
            uint32_t off = SWZ128((uint32_t)(row * 128 + ks * 32 + (lane >> 4) * 16));
            ldsm_x4(ah[t], xh + off);
        }
        int bg    = lane >> 3;
        int bn_in = ((bg >> 1) << 3) + (lane & 7);
        int bk    = ks * 32 + (bg & 1) * 16;

        uint32_t bh[2][4], bl[2][4];
#pragma unroll
        for (int j = 0; j < 2; ++j) {
            int n = wn * 32 + j * 16 + bn_in;
            uint32_t noff = SWZ128((uint32_t)(n * 128 + bk));
            ldsm_x4(bh[j], wh + noff);
            ldsm_x4(bl[j], wl + noff);
        }
#pragma unroll
        for (int t = 0; t < 2; ++t)
#pragma unroll
            for (int j = 0; j < 2; ++j) {
                mma_f16(c[t][2 * j + 0], ah[t], bh[j][0], bh[j][1]);
                mma_f16(c[t][2 * j + 1], ah[t], bh[j][2], bh[j][3]);
                mma_f16(c[t][2 * j + 0], ah[t], bl[j][0], bl[j][1]);
                mma_f16(c[t][2 * j + 1], ah[t], bl[j][2], bl[j][3]);
            }
    }
}

__global__ __launch_bounds__(512) void gemm_kernel(
    const float* __restrict__ bias,
    float*       __restrict__ out,
    int M)
{
    extern __shared__ char smem[];
    const uint32_t sb = smem_u32(smem);
    const int tid  = threadIdx.x;
    const int lane = tid & 31;
    const int wid  = tid >> 5;
    const int wm   = wid >> 2;
    const int wn   = wid & 3;
    const int m0   = blockIdx.x * MT;
    const int b    = blockIdx.x;

#pragma unroll
    for (int kt = 0; kt < 4; ++kt) {
        size_t xb = ((size_t)b * 4 + kt) * TILE_B;
        size_t wb = (size_t)kt * TILE_B;
#pragma unroll
        for (int j = 0; j < 2; ++j) {
            uint32_t o = (uint32_t)(j * 512 + tid) * 16;
            cp_async16(sb + kt * STAGE_B + o,          g_xh_img + xb + o);
            cp_async16(sb + kt * STAGE_B + 16384 + o,  g_Wh_img + wb + o);
            cp_async16(sb + kt * STAGE_B + 32768 + o,  g_Wl_img + wb + o);
        }
        cp_commit();
    }

    float c[2][4][4];
#pragma unroll
    for (int t = 0; t < 2; ++t)
#pragma unroll
        for (int j = 0; j < 4; ++j)
#pragma unroll
            for (int q = 0; q < 4; ++q) c[t][j][q] = 0.f;

    cp_wait<3>(); __syncthreads();
    mma_tile32(sb + 0 * STAGE_B, sb + 0 * STAGE_B + 16384, sb + 0 * STAGE_B + 32768,
               c, lane, wm, wn);
    cp_wait<2>(); __syncthreads();
    mma_tile32(sb + 1 * STAGE_B, sb + 1 * STAGE_B + 16384, sb + 1 * STAGE_B + 32768,
               c, lane, wm, wn);
    cp_wait<1>(); __syncthreads();
    mma_tile32(sb + 2 * STAGE_B, sb + 2 * STAGE_B + 16384, sb + 2 * STAGE_B + 32768,
               c, lane, wm, wn);
    cp_wait<0>(); __syncthreads();
    mma_tile32(sb + 3 * STAGE_B, sb + 3 * STAGE_B + 16384, sb + 3 * STAGE_B + 32768,
               c, lane, wm, wn);

    // ---- epilogue: bias + store ----
#pragma unroll
    for (int t = 0; t < 2; ++t) {
#pragma unroll
        for (int j = 0; j < 4; ++j) {
            int col = wn * 32 + (j >> 1) * 16 + (j & 1) * 8 + (lane & 3) * 2;
            float b0 = __ldg(bias + col);
            float b1 = __ldg(bias + col + 1);
            int r0 = m0 + wm * 32 + t * 16 + (lane >> 2);
            int r1 = r0 + 8;
            if (r0 < M) {
                float2 o = make_float2(c[t][j][0] + b0, c[t][j][1] + b1);
                *reinterpret_cast<float2*>(out + (size_t)r0 * D_FEAT + col) = o;
            }
            if (r1 < M) {
                float2 o = make_float2(c[t][j][2] + b0, c[t][j][3] + b1);
                *reinterpret_cast<float2*>(out + (size_t)r1 * D_FEAT + col) = o;
            }
        }
    }
}

// ===========================================================================
// Launch
// ===========================================================================
extern "C" void kernel_launch(void* const* d_in, const int* in_sizes, int n_in,
                              void* d_out, int out_size)
{
    const float* feat   = (const float*)d_in[0];
    const float* affine = (const float*)d_in[1];
    const int*   src    = (const int*)  d_in[2];
    const int*   dst    = (const int*)  d_in[3];
    const float* W      = (const float*)d_in[4];
    const float* bias   = (const float*)d_in[5];
    float*       out    = (float*)d_out;

    const int n_nodes = in_sizes[0] / D_FEAT;
    const int n_edges = in_sizes[1];

    cudaFuncSetAttribute(gemm_kernel,
                         cudaFuncAttributeMaxDynamicSharedMemorySize, SM_TOTAL);

    int rpb = ((n_edges + 3) / 4 + 255) / 256;     // rowptr blocks
    int fpb = (n_nodes * 16 + 255) / 256;          // featprep blocks (1 elem/thread)
    prep1_kernel<<<rpb + fpb + 16, 256>>>(
        reinterpret_cast<const float4*>(feat), dst, W,
        n_nodes, n_edges, rpb, fpb);

    agg_kernel<<<(n_nodes * 32 + 255) / 256, 256>>>(affine, src, n_nodes);

    gemm_kernel<<<(n_nodes + MT - 1) / MT, 512, SM_TOTAL>>>(bias, out, n_nodes);
}